// round 2
// baseline (speedup 1.0000x reference)
#include <cuda_runtime.h>
#include <math.h>
#include <stdint.h>

#define BNR 32768
#define HOFF 458752
#define KOFF 2555904

// ------------- scratch globals (no allocs allowed) -------------
__device__ __align__(16) float g_x1[BNR * 64];
__device__ __align__(16) float g_gx[BNR * 192];
__device__ __align__(16) float g_gh[BNR * 192];
__device__ __align__(16) float g_t1[BNR * 128];
__device__ __align__(16) float g_stats[1024];
__device__ __align__(16) float g_mean[BNR * 512];
__device__ __align__(16) float g_var[BNR * 512];
__device__ __align__(16) float g_aware[BNR * 512];
__device__ __align__(16) float g_att[BNR * 512];
__device__ __align__(16) float g_U[BNR * 128];
__device__ __align__(16) float g_V[BNR * 128];

// ------------- small elementwise kernels -------------
__global__ void zero_stats_k() { g_stats[threadIdx.x] = 0.f; }

__global__ void __launch_bounds__(256) gru_k(const float* __restrict__ hin,
                                             float* __restrict__ hout) {
    int idx = blockIdx.x * 256 + threadIdx.x;        // < 32768*64
    int r = idx >> 6, j = idx & 63;
    int base = r * 192 + j;
    float xr = g_gx[base], xz = g_gx[base + 64], xn = g_gx[base + 128];
    float hr = g_gh[base], hz = g_gh[base + 64], hn = g_gh[base + 128];
    float rr = 1.f / (1.f + expf(-(xr + hr)));
    float zz = 1.f / (1.f + expf(-(xz + hz)));
    float nn = tanhf(xn + rr * hn);
    float hi = hin[idx];
    hout[idx] = (1.f - zz) * nn + zz * hi;
}

__global__ void __launch_bounds__(128) ae_stats_k() {
    int c = threadIdx.x;
    size_t r0 = (size_t)blockIdx.x * 256;
    float s1 = 0.f, s2 = 0.f;
    for (int r = 0; r < 256; r++) {
        float v = g_t1[(r0 + r) * 128 + c];
        s1 += v; s2 += v * v;
    }
    atomicAdd(&g_stats[c], s1);
    atomicAdd(&g_stats[128 + c], s2);
}

__global__ void fin_ae_k() {
    int c = threadIdx.x;
    float m = g_stats[c] * (1.f / 32768.f);
    float v = g_stats[128 + c] * (1.f / 32768.f) - m * m;
    g_stats[256 + c] = m;
    g_stats[384 + c] = rsqrtf(v + 1e-5f);
}

__global__ void __launch_bounds__(256) bnact_k(const float* __restrict__ g,
                                               const float* __restrict__ be) {
    int i = blockIdx.x * 256 + threadIdx.x;          // < 32768*128
    int c = i & 127;
    float v = (g_t1[i] - g_stats[256 + c]) * g_stats[384 + c] * g[c] + be[c];
    g_t1[i] = v >= 0.f ? v : 0.01f * v;
}

__global__ void __launch_bounds__(256) aware_k(const float* __restrict__ noise) {
    int i = blockIdx.x * 256 + threadIdx.x;          // float4 index < 4194304
    float4 m = ((const float4*)g_mean)[i];
    float4 v = ((const float4*)g_var)[i];
    float4 n = ((const float4*)noise)[i];
    float4 o;
    o.x = m.x + sqrtf(v.x) * n.x;
    o.y = m.y + sqrtf(v.y) * n.y;
    o.z = m.z + sqrtf(v.z) * n.z;
    o.w = m.w + sqrtf(v.w) * n.w;
    ((float4*)g_aware)[i] = o;
}

__global__ void __launch_bounds__(128) inf_stats_k() {
    int c = threadIdx.x;
    int b0 = blockIdx.x * 32;
    float A1 = 0.f, A2 = 0.f;
    for (int b = b0; b < b0 + 32; b++) {
        float su = 0.f, su2 = 0.f, sv = 0.f, sv2 = 0.f;
        #pragma unroll
        for (int i = 0; i < 8; i++) {
            float u = g_U[(size_t)(b * 8 + i) * 128 + c];
            float v = g_V[(size_t)(b * 8 + i) * 128 + c];
            su += u; su2 += u * u;
            sv += v; sv2 += v * v;
        }
        A1 += 8.f * (su + sv);
        A2 += 8.f * (su2 + sv2) + 2.f * su * sv;
    }
    atomicAdd(&g_stats[512 + c], A1);
    atomicAdd(&g_stats[640 + c], A2);
}

__global__ void fin_inf_k() {
    int c = threadIdx.x;
    const float im = 1.f / 262144.f;
    float m = g_stats[512 + c] * im;
    float v = g_stats[640 + c] * im - m * m;
    g_stats[768 + c] = m;
    g_stats[896 + c] = rsqrtf(v + 1e-5f);
}

// ------------- generic tiled SGEMM: BM=BN=64, BK=16, 128 thr, TM=8 TN=4 -------
// EPI 0: +bias (bias may be null). EPI 1: relu(+bias).
// EPI 2: ae2 split: col<512 -> C=mean; col>=512 -> C2=max(exp(v),0.002)
template <int EPI>
__global__ void __launch_bounds__(128) gemm_k(
    const float* __restrict__ A, const float* __restrict__ B,
    const float* __restrict__ bias, float* __restrict__ C, float* __restrict__ C2,
    int M, int N, int K) {
    __shared__ __align__(16) float As[16][68];
    __shared__ __align__(16) float Bs[16][68];
    int t = threadIdx.x;
    int m0 = blockIdx.y * 64, n0 = blockIdx.x * 64;
    int tx = t & 15, ty = t >> 4;
    float acc[8][4];
    #pragma unroll
    for (int i = 0; i < 8; i++)
        #pragma unroll
        for (int j = 0; j < 4; j++) acc[i][j] = 0.f;

    for (int k0 = 0; k0 < K; k0 += 16) {
        #pragma unroll
        for (int u = 0; u < 2; u++) {
            int f = t * 2 + u;
            int row = f >> 2, kq = (f & 3) * 4;
            float4 v = *(const float4*)(A + (size_t)(m0 + row) * K + k0 + kq);
            As[kq][row] = v.x; As[kq + 1][row] = v.y;
            As[kq + 2][row] = v.z; As[kq + 3][row] = v.w;
        }
        #pragma unroll
        for (int u = 0; u < 2; u++) {
            int f = t * 2 + u;
            int row = f >> 4, cq = (f & 15) * 4;
            *(float4*)&Bs[row][cq] = *(const float4*)(B + (size_t)(k0 + row) * N + n0 + cq);
        }
        __syncthreads();
        #pragma unroll
        for (int kk = 0; kk < 16; kk++) {
            float b4[4], a8[8];
            *(float4*)b4 = *(float4*)&Bs[kk][tx * 4];
            *(float4*)a8 = *(float4*)&As[kk][ty * 8];
            *(float4*)(a8 + 4) = *(float4*)&As[kk][ty * 8 + 4];
            #pragma unroll
            for (int i = 0; i < 8; i++)
                #pragma unroll
                for (int j = 0; j < 4; j++) acc[i][j] += a8[i] * b4[j];
        }
        __syncthreads();
    }
    #pragma unroll
    for (int i = 0; i < 8; i++) {
        int row = m0 + ty * 8 + i;
        #pragma unroll
        for (int j = 0; j < 4; j++) {
            int col = n0 + tx * 4 + j;
            float v = acc[i][j] + (bias ? bias[col] : 0.f);
            if (EPI == 1) v = v > 0.f ? v : 0.f;
            if (EPI == 2) {
                if (col < 512) g_mean[(size_t)row * 512 + col] = v;
                else g_var[(size_t)row * 512 + col - 512] = fmaxf(expf(v), 0.002f);
            } else {
                C[(size_t)row * N + col] = v;
            }
        }
    }
}

// ------------- infer stage-2 GEMM fused with KLD (one block per batch b) -----
__global__ void __launch_bounds__(256) inf2_k(
    const float* __restrict__ w2, const float* __restrict__ b2,
    const float* __restrict__ gi, const float* __restrict__ bei,
    float* __restrict__ kout) {
    extern __shared__ __align__(16) float sm[];
    float* sW  = sm;                 // [128][132]
    float* sA2 = sW + 128 * 132;     // [64][130]
    float* sU  = sA2 + 64 * 130;     // [8][128]
    float* sV  = sU + 1024;
    float* sred = sV + 1024;         // 8
    int t = threadIdx.x, b = blockIdx.x;

    for (int i = t; i < 1024; i += 256) {
        sU[i] = g_U[(size_t)b * 1024 + i];
        sV[i] = g_V[(size_t)b * 1024 + i];
    }
    for (int i = t; i < 4096; i += 256) {       // 4096 float4 = 128x128
        int row = i >> 5, c4 = (i & 31) * 4;
        *(float4*)&sW[row * 132 + c4] = *(const float4*)(w2 + row * 128 + c4);
    }
    __syncthreads();
    for (int e = t; e < 8192; e += 256) {
        int row = e >> 7, c = e & 127;
        int i = row >> 3, j = row & 7;
        float v = (sU[i * 128 + c] + sV[j * 128 + c] - g_stats[768 + c]) *
                  g_stats[896 + c] * gi[c] + bei[c];
        sA2[row * 130 + c] = v >= 0.f ? v : 0.01f * v;
    }
    __syncthreads();

    int rg = t >> 4, cg = t & 15;
    float acc[4][8];
    #pragma unroll
    for (int i = 0; i < 4; i++)
        #pragma unroll
        for (int j = 0; j < 8; j++) acc[i][j] = 0.f;
    for (int kk = 0; kk < 128; kk++) {
        float a4[4], w8[8];
        #pragma unroll
        for (int i = 0; i < 4; i++) a4[i] = sA2[(rg * 4 + i) * 130 + kk];
        *(float4*)w8 = *(float4*)&sW[kk * 132 + cg * 8];
        *(float4*)(w8 + 4) = *(float4*)&sW[kk * 132 + cg * 8 + 4];
        #pragma unroll
        for (int i = 0; i < 4; i++)
            #pragma unroll
            for (int j = 0; j < 8; j++) acc[i][j] += a4[i] * w8[j];
    }
    __syncthreads();
    #pragma unroll
    for (int i = 0; i < 4; i++)
        #pragma unroll
        for (int j = 0; j < 8; j++)
            sA2[(rg * 4 + i) * 130 + cg * 8 + j] = acc[i][j] + b2[cg * 8 + j];
    __syncthreads();

    float s = 0.f;
    for (int e = t; e < 4096; e += 256) {
        int row = e >> 6, d = e & 63;
        float im = sA2[row * 130 + d];
        float iv = fmaxf(expf(sA2[row * 130 + 64 + d]), 0.002f);
        int i = row >> 3, j = row & 7;
        size_t gr = (size_t)(b * 8 + i) * 512 + j * 64 + d;
        float m = g_mean[gr], v = g_var[gr];
        float dd = m - im;
        s += 0.5f * (logf(iv) - logf(v)) + 0.5f * (v + dd * dd) / iv - 0.5f;
    }
    for (int off = 16; off; off >>= 1) s += __shfl_xor_sync(~0u, s, off);
    if ((t & 31) == 0) sred[t >> 5] = s;
    __syncthreads();
    if (t < 8) {
        s = sred[t];
        #pragma unroll
        for (int off = 4; off; off >>= 1) s += __shfl_xor_sync(0xffu, s, off);
        if (t == 0) kout[b] = s * (1.f / 4096.f);
    }
}

// ------------- fused attention: warp per row (8 tokens x 64 dim) -------------
#define AT_WARPS 6
#define WSCR 2944
__global__ void __launch_bounds__(192) attn_k(
    const float* __restrict__ wq, const float* __restrict__ wk,
    const float* __restrict__ wv, const float* __restrict__ wfc,
    const float* __restrict__ gln, const float* __restrict__ bln) {
    extern __shared__ __align__(16) float sm[];
    float* swq = sm;
    float* swk = swq + 8192;
    float* swv = swk + 8192;
    float* swfc = swv + 8192;
    float* sgln = swfc + 8192;
    float* sbln = sgln + 64;
    float* swarp = sbln + 64;
    int t = threadIdx.x, wid = t >> 5, lane = t & 31;

    for (int i = t; i < 8192; i += 192) {
        swq[i] = wq[i]; swk[i] = wk[i]; swv[i] = wv[i]; swfc[i] = wfc[i];
    }
    if (t < 64) { sgln[t] = gln[t]; sbln[t] = bln[t]; }
    __syncthreads();

    float* sA = swarp + wid * WSCR;   // 512
    float* bQ = sA + 512;             // 1056 (also bO[8][128])
    float* bK = bQ + 1056;            // 1056
    float* bP = bK + 1056;            // 288
    int sh = lane >> 3, st1 = lane & 7;
    int gw = blockIdx.x * AT_WARPS + wid;
    int nw = gridDim.x * AT_WARPS;

    for (int r = gw; r < BNR; r += nw) {
        const float* arow = g_aware + (size_t)r * 512;
        for (int i = lane; i < 128; i += 32)
            ((float4*)sA)[i] = ((const float4*)arow)[i];
        __syncwarp();

        // QKV: lane owns dim=lane of each head
        float aq[32], ak_[32], av_[32];
        #pragma unroll
        for (int i = 0; i < 32; i++) { aq[i] = 0.f; ak_[i] = 0.f; av_[i] = 0.f; }
        for (int k = 0; k < 64; k++) {
            float areg[8];
            #pragma unroll
            for (int tt = 0; tt < 8; tt++) areg[tt] = sA[tt * 64 + k];
            #pragma unroll
            for (int h = 0; h < 4; h++) {
                int wi = k * 128 + h * 32 + lane;
                float wqv = swq[wi], wkv = swk[wi], wvv = swv[wi];
                #pragma unroll
                for (int tt = 0; tt < 8; tt++) {
                    aq[tt * 4 + h] += areg[tt] * wqv;
                    ak_[tt * 4 + h] += areg[tt] * wkv;
                    av_[tt * 4 + h] += areg[tt] * wvv;
                }
            }
        }
        #pragma unroll
        for (int tt = 0; tt < 8; tt++)
            #pragma unroll
            for (int h = 0; h < 4; h++) {
                bQ[(h * 8 + tt) * 33 + lane] = aq[tt * 4 + h];
                bK[(h * 8 + tt) * 33 + lane] = ak_[tt * 4 + h];
            }
        __syncwarp();

        // scores: lane owns (head=sh, query token=st1)
        float qd[32];
        int qb = (sh * 8 + st1) * 33;
        #pragma unroll
        for (int d = 0; d < 32; d++) qd[d] = bQ[qb + d];
        float sc[8];
        #pragma unroll
        for (int t2 = 0; t2 < 8; t2++) {
            int kb = (sh * 8 + t2) * 33;
            float s = 0.f;
            #pragma unroll
            for (int d = 0; d < 32; d++) s += qd[d] * bK[kb + d];
            sc[t2] = s * 0.17677669529663687f;
        }
        float mx = sc[0];
        #pragma unroll
        for (int t2 = 1; t2 < 8; t2++) mx = fmaxf(mx, sc[t2]);
        float ssum = 0.f;
        #pragma unroll
        for (int t2 = 0; t2 < 8; t2++) { sc[t2] = __expf(sc[t2] - mx); ssum += sc[t2]; }
        float inv = 1.f / ssum;
        #pragma unroll
        for (int t2 = 0; t2 < 8; t2++)
            bP[(sh * 8 + st1) * 9 + t2] = sc[t2] * inv;
        __syncwarp();

        // O = P @ V (V from registers, P broadcast from smem)
        float oo[32];
        #pragma unroll
        for (int i = 0; i < 32; i++) oo[i] = 0.f;
        #pragma unroll
        for (int t2 = 0; t2 < 8; t2++)
            #pragma unroll
            for (int h = 0; h < 4; h++) {
                float vv = av_[t2 * 4 + h];
                int pb = h * 72 + t2;
                #pragma unroll
                for (int t1 = 0; t1 < 8; t1++)
                    oo[t1 * 4 + h] += bP[pb + t1 * 9] * vv;
            }
        #pragma unroll
        for (int tt = 0; tt < 8; tt++)
            #pragma unroll
            for (int h = 0; h < 4; h++)
                bQ[tt * 128 + h * 32 + lane] = oo[tt * 4 + h];   // bO
        __syncwarp();

        // fc + residual + LN
        float* outr = g_att + (size_t)r * 512;
        #pragma unroll
        for (int tt = 0; tt < 8; tt++) {
            float f0 = 0.f, f1 = 0.f;
            for (int c = 0; c < 128; c++) {
                float ov = bQ[tt * 128 + c];
                f0 += ov * swfc[c * 64 + lane];
                f1 += ov * swfc[c * 64 + lane + 32];
            }
            f0 += sA[tt * 64 + lane];
            f1 += sA[tt * 64 + lane + 32];
            float s1 = f0 + f1, s2 = f0 * f0 + f1 * f1;
            #pragma unroll
            for (int off = 16; off; off >>= 1) {
                s1 += __shfl_xor_sync(~0u, s1, off);
                s2 += __shfl_xor_sync(~0u, s2, off);
            }
            float mu = s1 * (1.f / 64.f);
            float var = s2 * (1.f / 64.f) - mu * mu;
            float is = rsqrtf(var + 1e-6f);
            outr[tt * 64 + lane] = (f0 - mu) * is * sgln[lane] + sbln[lane];
            outr[tt * 64 + lane + 32] = (f1 - mu) * is * sgln[lane + 32] + sbln[lane + 32];
        }
        __syncwarp();
    }
}

// ------------- mlp2: q = [h | att] @ w_mlp2 + b -------------
__global__ void __launch_bounds__(128) mlp2_k(
    const float* __restrict__ h, const float* __restrict__ w,
    const float* __restrict__ b, float* __restrict__ out) {
    __shared__ __align__(16) float As[128][68];
    __shared__ __align__(16) float Ws[64][16];
    __shared__ float sb[14];
    int t = threadIdx.x;
    int r0 = blockIdx.x * 128;
    if (t < 14) sb[t] = b[t];
    int rg = t >> 2, cg = t & 3;
    float acc[4][4];
    #pragma unroll
    for (int i = 0; i < 4; i++)
        #pragma unroll
        for (int j = 0; j < 4; j++) acc[i][j] = 0.f;

    for (int k0 = 0; k0 < 576; k0 += 64) {
        #pragma unroll
        for (int u = 0; u < 16; u++) {
            int f = u * 128 + t;
            int row = f >> 4, cq = (f & 15) * 4;
            float4 v;
            if (k0 == 0) v = *(const float4*)(h + (size_t)(r0 + row) * 64 + cq);
            else v = *(const float4*)(g_att + (size_t)(r0 + row) * 512 + (k0 - 64) + cq);
            *(float4*)&As[row][cq] = v;
        }
        for (int i = t; i < 1024; i += 128) {
            int row = i >> 4, c = i & 15;
            Ws[row][c] = (c < 14) ? w[(k0 + row) * 14 + c] : 0.f;
        }
        __syncthreads();
        #pragma unroll
        for (int kk = 0; kk < 64; kk++) {
            float a4[4], w4[4];
            #pragma unroll
            for (int i = 0; i < 4; i++) a4[i] = As[rg * 4 + i][kk];
            *(float4*)w4 = *(float4*)&Ws[kk][cg * 4];
            #pragma unroll
            for (int i = 0; i < 4; i++)
                #pragma unroll
                for (int j = 0; j < 4; j++) acc[i][j] += a4[i] * w4[j];
        }
        __syncthreads();
    }
    #pragma unroll
    for (int i = 0; i < 4; i++) {
        int row = r0 + rg * 4 + i;
        #pragma unroll
        for (int j = 0; j < 4; j++) {
            int col = cg * 4 + j;
            if (col < 14) out[(size_t)row * 14 + col] = acc[i][j] + sb[col];
        }
    }
}

// ------------- launcher -------------
extern "C" void kernel_launch(void* const* d_in, const int* in_sizes, int n_in,
                              void* d_out, int out_size) {
    const float* in_x   = (const float*)d_in[0];
    const float* hid    = (const float*)d_in[1];
    const float* noise  = (const float*)d_in[2];
    const float* w_mlp1 = (const float*)d_in[3];
    const float* b_mlp1 = (const float*)d_in[4];
    const float* w_ih   = (const float*)d_in[5];
    const float* b_ih   = (const float*)d_in[6];
    const float* w_hh   = (const float*)d_in[7];
    const float* b_hh   = (const float*)d_in[8];
    const float* w_ae1  = (const float*)d_in[9];
    const float* b_ae1  = (const float*)d_in[10];
    const float* g_ae   = (const float*)d_in[11];
    const float* be_ae  = (const float*)d_in[12];
    const float* w_ae2  = (const float*)d_in[13];
    const float* b_ae2  = (const float*)d_in[14];
    const float* w_in1  = (const float*)d_in[15];
    const float* b_in1  = (const float*)d_in[16];
    const float* g_in   = (const float*)d_in[17];
    const float* be_in  = (const float*)d_in[18];
    const float* w_in2  = (const float*)d_in[19];
    const float* b_in2  = (const float*)d_in[20];
    const float* w_q    = (const float*)d_in[21];
    const float* w_k    = (const float*)d_in[22];
    const float* w_v    = (const float*)d_in[23];
    const float* w_fc   = (const float*)d_in[24];
    const float* gln    = (const float*)d_in[25];
    const float* bln    = (const float*)d_in[26];
    const float* w_mlp2 = (const float*)d_in[27];
    const float* b_mlp2 = (const float*)d_in[28];

    float* out  = (float*)d_out;
    float* qout = out;
    float* hout = out + HOFF;
    float* kout = out + KOFF;

    void *px1, *pt1, *pU, *pV;
    cudaGetSymbolAddress(&px1, g_x1);
    cudaGetSymbolAddress(&pt1, g_t1);
    cudaGetSymbolAddress(&pU, g_U);
    cudaGetSymbolAddress(&pV, g_V);
    void *pgx, *pgh;
    cudaGetSymbolAddress(&pgx, g_gx);
    cudaGetSymbolAddress(&pgh, g_gh);

    size_t inf2_smem = (size_t)(128 * 132 + 64 * 130 + 1024 + 1024 + 8) * 4;
    size_t attn_smem = (size_t)(8192 * 4 + 128 + AT_WARPS * WSCR) * 4;
    cudaFuncSetAttribute(inf2_k, cudaFuncAttributeMaxDynamicSharedMemorySize, (int)inf2_smem);
    cudaFuncSetAttribute(attn_k, cudaFuncAttributeMaxDynamicSharedMemorySize, (int)attn_smem);

    // 1. x1 = relu(in @ w_mlp1 + b)
    gemm_k<1><<<dim3(1, 512), 128>>>(in_x, w_mlp1, b_mlp1, (float*)px1, nullptr, BNR, 64, 96);
    // 2. gates
    gemm_k<0><<<dim3(3, 512), 128>>>((const float*)px1, w_ih, b_ih, (float*)pgx, nullptr, BNR, 192, 64);
    gemm_k<0><<<dim3(3, 512), 128>>>(hid, w_hh, b_hh, (float*)pgh, nullptr, BNR, 192, 64);
    // 3. GRU -> h (into d_out)
    gru_k<<<8192, 256>>>(hid, hout);
    // 4. ae1
    gemm_k<0><<<dim3(2, 512), 128>>>(hout, w_ae1, b_ae1, (float*)pt1, nullptr, BNR, 128, 64);
    // 5. BN stats
    zero_stats_k<<<1, 1024>>>();
    ae_stats_k<<<128, 128>>>();
    fin_ae_k<<<1, 128>>>();
    bnact_k<<<16384, 256>>>(g_ae, be_ae);
    // 6. ae2 -> mean/var
    gemm_k<2><<<dim3(16, 512), 128>>>((const float*)pt1, w_ae2, b_ae2, nullptr, nullptr, BNR, 1024, 128);
    // 7. awareness
    aware_k<<<16384, 256>>>(noise);
    // 8. U, V
    gemm_k<0><<<dim3(2, 512), 128>>>(hout, w_in1, nullptr, (float*)pU, nullptr, BNR, 128, 64);
    gemm_k<0><<<dim3(2, 512), 128>>>(hout, w_in1 + 64 * 128, b_in1, (float*)pV, nullptr, BNR, 128, 64);
    // 9. infer BN stats
    inf_stats_k<<<128, 128>>>();
    fin_inf_k<<<1, 128>>>();
    // 10. infer stage-2 + KLD
    inf2_k<<<4096, 256, inf2_smem>>>(w_in2, b_in2, g_in, be_in, kout);
    // 11. attention
    attn_k<<<296, 192, attn_smem>>>(w_q, w_k, w_v, w_fc, gln, bln);
    // 12. mlp2
    mlp2_k<<<256, 128>>>(hout, w_mlp2, b_mlp2, qout);
}

// round 4
// speedup vs baseline: 1.2557x; 1.2557x over previous
#include <cuda_runtime.h>
#include <math.h>
#include <stdint.h>

#define BNR 32768
#define HOFF 458752
#define KOFF 2555904

// ------------- scratch globals (no allocs allowed) -------------
__device__ __align__(16) float g_x1[BNR * 64];
__device__ __align__(16) float g_gx[BNR * 192];
__device__ __align__(16) float g_gh[BNR * 192];
__device__ __align__(16) float g_t1[BNR * 128];
__device__ __align__(16) float g_stats[1024];
__device__ __align__(16) float g_mean[BNR * 512];
__device__ __align__(16) float g_var[BNR * 512];
__device__ __align__(16) float g_aware[BNR * 512];
__device__ __align__(16) float g_att[BNR * 512];
__device__ __align__(16) float g_U[BNR * 128];
__device__ __align__(16) float g_V[BNR * 128];

// ------------- tf32 mma helpers -------------
__device__ __forceinline__ float f2tf(float x) {
    uint32_t r;
    asm("cvt.rna.tf32.f32 %0, %1;" : "=r"(r) : "f"(x));
    return __uint_as_float(r);
}
__device__ __forceinline__ void mma_tf32(float* c, const uint32_t* a, const uint32_t* b) {
    asm volatile(
        "mma.sync.aligned.m16n8k8.row.col.f32.tf32.tf32.f32 "
        "{%0,%1,%2,%3}, {%4,%5,%6,%7}, {%8,%9}, {%0,%1,%2,%3};"
        : "+f"(c[0]), "+f"(c[1]), "+f"(c[2]), "+f"(c[3])
        : "r"(a[0]), "r"(a[1]), "r"(a[2]), "r"(a[3]), "r"(b[0]), "r"(b[1]));
}

// ------------- small elementwise kernels -------------
__global__ void zero_stats_k() { g_stats[threadIdx.x] = 0.f; }

__global__ void __launch_bounds__(256) gru_k(const float* __restrict__ hin,
                                             float* __restrict__ hout) {
    int idx = blockIdx.x * 256 + threadIdx.x;        // < 32768*64
    int r = idx >> 6, j = idx & 63;
    int base = r * 192 + j;
    float xr = g_gx[base], xz = g_gx[base + 64], xn = g_gx[base + 128];
    float hr = g_gh[base], hz = g_gh[base + 64], hn = g_gh[base + 128];
    float rr = 1.f / (1.f + expf(-(xr + hr)));
    float zz = 1.f / (1.f + expf(-(xz + hz)));
    float nn = tanhf(xn + rr * hn);
    float hi = hin[idx];
    hout[idx] = (1.f - zz) * nn + zz * hi;
}

__global__ void __launch_bounds__(128) ae_stats_k() {
    int c = threadIdx.x;
    size_t r0 = (size_t)blockIdx.x * 256;
    float s1 = 0.f, s2 = 0.f;
    for (int r = 0; r < 256; r++) {
        float v = g_t1[(r0 + r) * 128 + c];
        s1 += v; s2 += v * v;
    }
    atomicAdd(&g_stats[c], s1);
    atomicAdd(&g_stats[128 + c], s2);
}

__global__ void fin_ae_k() {
    int c = threadIdx.x;
    float m = g_stats[c] * (1.f / 32768.f);
    float v = g_stats[128 + c] * (1.f / 32768.f) - m * m;
    g_stats[256 + c] = m;
    g_stats[384 + c] = rsqrtf(v + 1e-5f);
}

__global__ void __launch_bounds__(256) aware_k(const float* __restrict__ noise) {
    int i = blockIdx.x * 256 + threadIdx.x;          // float4 index < 4194304
    float4 m = ((const float4*)g_mean)[i];
    float4 v = ((const float4*)g_var)[i];
    float4 n = ((const float4*)noise)[i];
    float4 o;
    o.x = m.x + sqrtf(v.x) * n.x;
    o.y = m.y + sqrtf(v.y) * n.y;
    o.z = m.z + sqrtf(v.z) * n.z;
    o.w = m.w + sqrtf(v.w) * n.w;
    ((float4*)g_aware)[i] = o;
}

__global__ void __launch_bounds__(128) inf_stats_k() {
    int c = threadIdx.x;
    int b0 = blockIdx.x * 32;
    float A1 = 0.f, A2 = 0.f;
    for (int b = b0; b < b0 + 32; b++) {
        float su = 0.f, su2 = 0.f, sv = 0.f, sv2 = 0.f;
        #pragma unroll
        for (int i = 0; i < 8; i++) {
            float u = g_U[(size_t)(b * 8 + i) * 128 + c];
            float v = g_V[(size_t)(b * 8 + i) * 128 + c];
            su += u; su2 += u * u;
            sv += v; sv2 += v * v;
        }
        A1 += 8.f * (su + sv);
        A2 += 8.f * (su2 + sv2) + 2.f * su * sv;
    }
    atomicAdd(&g_stats[512 + c], A1);
    atomicAdd(&g_stats[640 + c], A2);
}

__global__ void fin_inf_k() {
    int c = threadIdx.x;
    const float im = 1.f / 262144.f;
    float m = g_stats[512 + c] * im;
    float v = g_stats[640 + c] * im - m * m;
    g_stats[768 + c] = m;
    g_stats[896 + c] = rsqrtf(v + 1e-5f);
}

// ------------- generic tiled SGEMM (small GEMMs): BM=BN=64, BK=16 -------------
template <int EPI>
__global__ void __launch_bounds__(128) gemm_k(
    const float* __restrict__ A, const float* __restrict__ B,
    const float* __restrict__ bias, float* __restrict__ C,
    int M, int N, int K) {
    __shared__ __align__(16) float As[16][68];
    __shared__ __align__(16) float Bs[16][68];
    int t = threadIdx.x;
    int m0 = blockIdx.y * 64, n0 = blockIdx.x * 64;
    int tx = t & 15, ty = t >> 4;
    float acc[8][4];
    #pragma unroll
    for (int i = 0; i < 8; i++)
        #pragma unroll
        for (int j = 0; j < 4; j++) acc[i][j] = 0.f;

    for (int k0 = 0; k0 < K; k0 += 16) {
        #pragma unroll
        for (int u = 0; u < 2; u++) {
            int f = t * 2 + u;
            int row = f >> 2, kq = (f & 3) * 4;
            float4 v = *(const float4*)(A + (size_t)(m0 + row) * K + k0 + kq);
            As[kq][row] = v.x; As[kq + 1][row] = v.y;
            As[kq + 2][row] = v.z; As[kq + 3][row] = v.w;
        }
        #pragma unroll
        for (int u = 0; u < 2; u++) {
            int f = t * 2 + u;
            int row = f >> 4, cq = (f & 15) * 4;
            *(float4*)&Bs[row][cq] = *(const float4*)(B + (size_t)(k0 + row) * N + n0 + cq);
        }
        __syncthreads();
        #pragma unroll
        for (int kk = 0; kk < 16; kk++) {
            float b4[4], a8[8];
            *(float4*)b4 = *(float4*)&Bs[kk][tx * 4];
            *(float4*)a8 = *(float4*)&As[kk][ty * 8];
            *(float4*)(a8 + 4) = *(float4*)&As[kk][ty * 8 + 4];
            #pragma unroll
            for (int i = 0; i < 8; i++)
                #pragma unroll
                for (int j = 0; j < 4; j++) acc[i][j] += a8[i] * b4[j];
        }
        __syncthreads();
    }
    #pragma unroll
    for (int i = 0; i < 8; i++) {
        int row = m0 + ty * 8 + i;
        #pragma unroll
        for (int j = 0; j < 4; j++) {
            int col = n0 + tx * 4 + j;
            float v = acc[i][j] + (bias ? bias[col] : 0.f);
            if (EPI == 1) v = v > 0.f ? v : 0.f;
            C[(size_t)row * N + col] = v;
        }
    }
}

// ------------- ae2: tf32 mma GEMM, BN+lrelu fused into A load ---------------
// M=32768, N=1024, K=128. BM=128, BN=128, BK=32. 256 thr, 8 warps (4m x 2n).
__global__ void __launch_bounds__(256) ae2_k(
    const float* __restrict__ Araw, const float* __restrict__ Bw,
    const float* __restrict__ bias,
    const float* __restrict__ gg, const float* __restrict__ bb) {
    __shared__ __align__(16) float As[128 * 36];   // stride 36 (==4 mod 32)
    __shared__ __align__(16) float Bs[32 * 136];   // stride 136 (==8 mod 32)
    __shared__ float sScale[128], sShift[128];
    int t = threadIdx.x, wid = t >> 5, lane = t & 31;
    int g = lane >> 2, tg = lane & 3;
    int m0 = blockIdx.y * 128, n0 = blockIdx.x * 128;
    int m0w = (wid & 3) * 32, n0w = (wid >> 2) * 64;

    if (t < 128) {
        float sc = g_stats[384 + t] * gg[t];
        sScale[t] = sc;
        sShift[t] = bb[t] - g_stats[256 + t] * sc;
    }
    __syncthreads();

    float acc[2][8][4];
    #pragma unroll
    for (int i = 0; i < 2; i++)
        #pragma unroll
        for (int j = 0; j < 8; j++)
            #pragma unroll
            for (int q = 0; q < 4; q++) acc[i][j][q] = 0.f;

    for (int k0 = 0; k0 < 128; k0 += 32) {
        // A tile: 128x32, BN + lrelu + tf32 round
        #pragma unroll
        for (int u = 0; u < 4; u++) {
            int idx = t + u * 256;
            int row = idx >> 3, c4 = (idx & 7) * 4;
            float4 v = *(const float4*)(Araw + (size_t)(m0 + row) * 128 + k0 + c4);
            float vv[4] = {v.x, v.y, v.z, v.w};
            #pragma unroll
            for (int jj = 0; jj < 4; jj++) {
                int col = k0 + c4 + jj;
                float x = vv[jj] * sScale[col] + sShift[col];
                x = x >= 0.f ? x : 0.01f * x;
                As[row * 36 + c4 + jj] = f2tf(x);
            }
        }
        // B tile: 32x128
        #pragma unroll
        for (int u = 0; u < 4; u++) {
            int idx = t + u * 256;
            int kr = idx >> 5, n4 = (idx & 31) * 4;
            float4 v = *(const float4*)(Bw + (size_t)(k0 + kr) * 1024 + n0 + n4);
            Bs[kr * 136 + n4 + 0] = f2tf(v.x);
            Bs[kr * 136 + n4 + 1] = f2tf(v.y);
            Bs[kr * 136 + n4 + 2] = f2tf(v.z);
            Bs[kr * 136 + n4 + 3] = f2tf(v.w);
        }
        __syncthreads();
        #pragma unroll
        for (int k8 = 0; k8 < 4; k8++) {
            int kb = k8 * 8;
            uint32_t af[2][4];
            #pragma unroll
            for (int i = 0; i < 2; i++) {
                int base = (m0w + i * 16 + g) * 36 + kb + tg;
                af[i][0] = __float_as_uint(As[base]);
                af[i][1] = __float_as_uint(As[base + 8 * 36]);
                af[i][2] = __float_as_uint(As[base + 4]);
                af[i][3] = __float_as_uint(As[base + 8 * 36 + 4]);
            }
            #pragma unroll
            for (int j = 0; j < 8; j++) {
                uint32_t bf[2];
                int nb = n0w + j * 8 + g;
                bf[0] = __float_as_uint(Bs[(kb + tg) * 136 + nb]);
                bf[1] = __float_as_uint(Bs[(kb + tg + 4) * 136 + nb]);
                mma_tf32(acc[0][j], af[0], bf);
                mma_tf32(acc[1][j], af[1], bf);
            }
        }
        __syncthreads();
    }
    // epilogue: whole block is mean (n0<512) or var (n0>=512)
    bool isvar = (n0 >= 512);
    #pragma unroll
    for (int i = 0; i < 2; i++) {
        #pragma unroll
        for (int j = 0; j < 8; j++) {
            int col = n0 + n0w + j * 8 + 2 * tg;
            float b0 = bias[col], b1 = bias[col + 1];
            int r0 = m0 + m0w + i * 16 + g;
            float v00 = acc[i][j][0] + b0, v01 = acc[i][j][1] + b1;
            float v10 = acc[i][j][2] + b0, v11 = acc[i][j][3] + b1;
            if (isvar) {
                int c = col - 512;
                *(float2*)&g_var[(size_t)r0 * 512 + c] =
                    make_float2(fmaxf(expf(v00), 0.002f), fmaxf(expf(v01), 0.002f));
                *(float2*)&g_var[(size_t)(r0 + 8) * 512 + c] =
                    make_float2(fmaxf(expf(v10), 0.002f), fmaxf(expf(v11), 0.002f));
            } else {
                *(float2*)&g_mean[(size_t)r0 * 512 + col] = make_float2(v00, v01);
                *(float2*)&g_mean[(size_t)(r0 + 8) * 512 + col] = make_float2(v10, v11);
            }
        }
    }
}

// ------------- infer stage-2 (tf32 mma) fused with KLD (one block per b) -----
__global__ void __launch_bounds__(256) inf2_k(
    const float* __restrict__ w2, const float* __restrict__ b2,
    const float* __restrict__ gi, const float* __restrict__ bei,
    float* __restrict__ kout) {
    extern __shared__ __align__(16) float sm[];
    float* sW  = sm;                  // [128][136]
    float* sA2 = sW + 128 * 136;      // [64][132]
    float* sU  = sA2 + 64 * 132;      // [8][128]
    float* sV  = sU + 1024;
    float* sred = sV + 1024;          // 8
    int t = threadIdx.x, b = blockIdx.x;
    int wid = t >> 5, lane = t & 31;
    int g = lane >> 2, tg = lane & 3;

    for (int i = t; i < 1024; i += 256) {
        sU[i] = g_U[(size_t)b * 1024 + i];
        sV[i] = g_V[(size_t)b * 1024 + i];
    }
    #pragma unroll
    for (int u = 0; u < 16; u++) {                 // 128x128 w2 -> tf32 smem
        int idx = t + u * 256;
        int row = idx >> 5, c4 = (idx & 31) * 4;
        float4 v = *(const float4*)(w2 + row * 128 + c4);
        sW[row * 136 + c4 + 0] = f2tf(v.x);
        sW[row * 136 + c4 + 1] = f2tf(v.y);
        sW[row * 136 + c4 + 2] = f2tf(v.z);
        sW[row * 136 + c4 + 3] = f2tf(v.w);
    }
    __syncthreads();
    for (int e = t; e < 8192; e += 256) {
        int row = e >> 7, c = e & 127;
        int i = row >> 3, j = row & 7;
        float v = (sU[i * 128 + c] + sV[j * 128 + c] - g_stats[768 + c]) *
                  g_stats[896 + c] * gi[c] + bei[c];
        v = v >= 0.f ? v : 0.01f * v;
        sA2[row * 132 + c] = f2tf(v);
    }
    __syncthreads();

    // GEMM: D(64x128) = A2(64x128) @ W2(128x128); warp: m-tile (wid&3), n-half (wid>>2)
    int mt = wid & 3, n0w = (wid >> 2) * 64;
    float acc[8][4];
    #pragma unroll
    for (int j = 0; j < 8; j++)
        #pragma unroll
        for (int q = 0; q < 4; q++) acc[j][q] = 0.f;
    #pragma unroll
    for (int k8 = 0; k8 < 16; k8++) {
        int kb = k8 * 8;
        uint32_t af[4];
        int base = (mt * 16 + g) * 132 + kb + tg;
        af[0] = __float_as_uint(sA2[base]);
        af[1] = __float_as_uint(sA2[base + 8 * 132]);
        af[2] = __float_as_uint(sA2[base + 4]);
        af[3] = __float_as_uint(sA2[base + 8 * 132 + 4]);
        #pragma unroll
        for (int j = 0; j < 8; j++) {
            uint32_t bf[2];
            int nb = n0w + j * 8 + g;
            bf[0] = __float_as_uint(sW[(kb + tg) * 136 + nb]);
            bf[1] = __float_as_uint(sW[(kb + tg + 4) * 136 + nb]);
            mma_tf32(acc[j], af, bf);
        }
    }
    __syncthreads();   // all reads of sA2 done; safe to overwrite with D
    #pragma unroll
    for (int j = 0; j < 8; j++) {
        int col = n0w + j * 8 + 2 * tg;
        int r0 = mt * 16 + g;
        sA2[r0 * 132 + col] = acc[j][0] + b2[col];
        sA2[r0 * 132 + col + 1] = acc[j][1] + b2[col + 1];
        sA2[(r0 + 8) * 132 + col] = acc[j][2] + b2[col];
        sA2[(r0 + 8) * 132 + col + 1] = acc[j][3] + b2[col + 1];
    }
    __syncthreads();

    float s = 0.f;
    for (int e = t; e < 4096; e += 256) {
        int row = e >> 6, d = e & 63;
        float im = sA2[row * 132 + d];
        float iv = fmaxf(expf(sA2[row * 132 + 64 + d]), 0.002f);
        int i = row >> 3, j = row & 7;
        size_t gr = (size_t)(b * 8 + i) * 512 + j * 64 + d;
        float m = g_mean[gr], v = g_var[gr];
        float dd = m - im;
        s += 0.5f * (logf(iv) - logf(v)) + 0.5f * (v + dd * dd) / iv - 0.5f;
    }
    for (int off = 16; off; off >>= 1) s += __shfl_xor_sync(~0u, s, off);
    if ((t & 31) == 0) sred[t >> 5] = s;
    __syncthreads();
    if (t < 8) {
        s = sred[t];
        #pragma unroll
        for (int off = 4; off; off >>= 1) s += __shfl_xor_sync(0xffu, s, off);
        if (t == 0) kout[b] = s * (1.f / 4096.f);
    }
}

// ------------- fused attention: warp per row (8 tokens x 64 dim) -------------
#define AT_WARPS 6
#define WSCR 2944
__global__ void __launch_bounds__(192) attn_k(
    const float* __restrict__ wq, const float* __restrict__ wk,
    const float* __restrict__ wv, const float* __restrict__ wfc,
    const float* __restrict__ gln, const float* __restrict__ bln) {
    extern __shared__ __align__(16) float sm[];
    float* swq = sm;
    float* swk = swq + 8192;
    float* swv = swk + 8192;
    float* swfc = swv + 8192;
    float* sgln = swfc + 8192;
    float* sbln = sgln + 64;
    float* swarp = sbln + 64;
    int t = threadIdx.x, wid = t >> 5, lane = t & 31;

    for (int i = t; i < 8192; i += 192) {
        swq[i] = wq[i]; swk[i] = wk[i]; swv[i] = wv[i]; swfc[i] = wfc[i];
    }
    if (t < 64) { sgln[t] = gln[t]; sbln[t] = bln[t]; }
    __syncthreads();

    float* sA = swarp + wid * WSCR;   // 512
    float* bQ = sA + 512;             // 1056 (also bO[8][128])
    float* bK = bQ + 1056;            // 1056
    float* bP = bK + 1056;            // 288
    int sh = lane >> 3, st1 = lane & 7;
    int gw = blockIdx.x * AT_WARPS + wid;
    int nw = gridDim.x * AT_WARPS;

    for (int r = gw; r < BNR; r += nw) {
        const float* arow = g_aware + (size_t)r * 512;
        for (int i = lane; i < 128; i += 32)
            ((float4*)sA)[i] = ((const float4*)arow)[i];
        __syncwarp();

        float aq[32], ak_[32], av_[32];
        #pragma unroll
        for (int i = 0; i < 32; i++) { aq[i] = 0.f; ak_[i] = 0.f; av_[i] = 0.f; }
        for (int k = 0; k < 64; k++) {
            float areg[8];
            #pragma unroll
            for (int tt = 0; tt < 8; tt++) areg[tt] = sA[tt * 64 + k];
            #pragma unroll
            for (int h = 0; h < 4; h++) {
                int wi = k * 128 + h * 32 + lane;
                float wqv = swq[wi], wkv = swk[wi], wvv = swv[wi];
                #pragma unroll
                for (int tt = 0; tt < 8; tt++) {
                    aq[tt * 4 + h] += areg[tt] * wqv;
                    ak_[tt * 4 + h] += areg[tt] * wkv;
                    av_[tt * 4 + h] += areg[tt] * wvv;
                }
            }
        }
        #pragma unroll
        for (int tt = 0; tt < 8; tt++)
            #pragma unroll
            for (int h = 0; h < 4; h++) {
                bQ[(h * 8 + tt) * 33 + lane] = aq[tt * 4 + h];
                bK[(h * 8 + tt) * 33 + lane] = ak_[tt * 4 + h];
            }
        __syncwarp();

        float qd[32];
        int qb = (sh * 8 + st1) * 33;
        #pragma unroll
        for (int d = 0; d < 32; d++) qd[d] = bQ[qb + d];
        float sc[8];
        #pragma unroll
        for (int t2 = 0; t2 < 8; t2++) {
            int kb = (sh * 8 + t2) * 33;
            float s = 0.f;
            #pragma unroll
            for (int d = 0; d < 32; d++) s += qd[d] * bK[kb + d];
            sc[t2] = s * 0.17677669529663687f;
        }
        float mx = sc[0];
        #pragma unroll
        for (int t2 = 1; t2 < 8; t2++) mx = fmaxf(mx, sc[t2]);
        float ssum = 0.f;
        #pragma unroll
        for (int t2 = 0; t2 < 8; t2++) { sc[t2] = __expf(sc[t2] - mx); ssum += sc[t2]; }
        float inv = 1.f / ssum;
        #pragma unroll
        for (int t2 = 0; t2 < 8; t2++)
            bP[(sh * 8 + st1) * 9 + t2] = sc[t2] * inv;
        __syncwarp();

        float oo[32];
        #pragma unroll
        for (int i = 0; i < 32; i++) oo[i] = 0.f;
        #pragma unroll
        for (int t2 = 0; t2 < 8; t2++)
            #pragma unroll
            for (int h = 0; h < 4; h++) {
                float vv = av_[t2 * 4 + h];
                int pb = h * 72 + t2;
                #pragma unroll
                for (int t1 = 0; t1 < 8; t1++)
                    oo[t1 * 4 + h] += bP[pb + t1 * 9] * vv;
            }
        #pragma unroll
        for (int tt = 0; tt < 8; tt++)
            #pragma unroll
            for (int h = 0; h < 4; h++)
                bQ[tt * 128 + h * 32 + lane] = oo[tt * 4 + h];   // bO
        __syncwarp();

        float* outr = g_att + (size_t)r * 512;
        #pragma unroll
        for (int tt = 0; tt < 8; tt++) {
            float f0 = 0.f, f1 = 0.f;
            for (int c = 0; c < 128; c++) {
                float ov = bQ[tt * 128 + c];
                f0 += ov * swfc[c * 64 + lane];
                f1 += ov * swfc[c * 64 + lane + 32];
            }
            f0 += sA[tt * 64 + lane];
            f1 += sA[tt * 64 + lane + 32];
            float s1 = f0 + f1, s2 = f0 * f0 + f1 * f1;
            #pragma unroll
            for (int off = 16; off; off >>= 1) {
                s1 += __shfl_xor_sync(~0u, s1, off);
                s2 += __shfl_xor_sync(~0u, s2, off);
            }
            float mu = s1 * (1.f / 64.f);
            float var = s2 * (1.f / 64.f) - mu * mu;
            float is = rsqrtf(var + 1e-6f);
            outr[tt * 64 + lane] = (f0 - mu) * is * sgln[lane] + sbln[lane];
            outr[tt * 64 + lane + 32] = (f1 - mu) * is * sgln[lane + 32] + sbln[lane + 32];
        }
        __syncwarp();
    }
}

// ------------- mlp2: q = [h | att] @ w_mlp2 + b -------------
__global__ void __launch_bounds__(128) mlp2_k(
    const float* __restrict__ h, const float* __restrict__ w,
    const float* __restrict__ b, float* __restrict__ out) {
    __shared__ __align__(16) float As[128][68];
    __shared__ __align__(16) float Ws[64][16];
    __shared__ float sb[14];
    int t = threadIdx.x;
    int r0 = blockIdx.x * 128;
    if (t < 14) sb[t] = b[t];
    int rg = t >> 2, cg = t & 3;
    float acc[4][4];
    #pragma unroll
    for (int i = 0; i < 4; i++)
        #pragma unroll
        for (int j = 0; j < 4; j++) acc[i][j] = 0.f;

    for (int k0 = 0; k0 < 576; k0 += 64) {
        #pragma unroll
        for (int u = 0; u < 16; u++) {
            int f = u * 128 + t;
            int row = f >> 4, cq = (f & 15) * 4;
            float4 v;
            if (k0 == 0) v = *(const float4*)(h + (size_t)(r0 + row) * 64 + cq);
            else v = *(const float4*)(g_att + (size_t)(r0 + row) * 512 + (k0 - 64) + cq);
            *(float4*)&As[row][cq] = v;
        }
        for (int i = t; i < 1024; i += 128) {
            int row = i >> 4, c = i & 15;
            Ws[row][c] = (c < 14) ? w[(k0 + row) * 14 + c] : 0.f;
        }
        __syncthreads();
        #pragma unroll
        for (int kk = 0; kk < 64; kk++) {
            float a4[4], w4[4];
            #pragma unroll
            for (int i = 0; i < 4; i++) a4[i] = As[rg * 4 + i][kk];
            *(float4*)w4 = *(float4*)&Ws[kk][cg * 4];
            #pragma unroll
            for (int i = 0; i < 4; i++)
                #pragma unroll
                for (int j = 0; j < 4; j++) acc[i][j] += a4[i] * w4[j];
        }
        __syncthreads();
    }
    #pragma unroll
    for (int i = 0; i < 4; i++) {
        int row = r0 + rg * 4 + i;
        #pragma unroll
        for (int j = 0; j < 4; j++) {
            int col = cg * 4 + j;
            if (col < 14) out[(size_t)row * 14 + col] = acc[i][j] + sb[col];
        }
    }
}

// ------------- launcher -------------
extern "C" void kernel_launch(void* const* d_in, const int* in_sizes, int n_in,
                              void* d_out, int out_size) {
    const float* in_x   = (const float*)d_in[0];
    const float* hid    = (const float*)d_in[1];
    const float* noise  = (const float*)d_in[2];
    const float* w_mlp1 = (const float*)d_in[3];
    const float* b_mlp1 = (const float*)d_in[4];
    const float* w_ih   = (const float*)d_in[5];
    const float* b_ih   = (const float*)d_in[6];
    const float* w_hh   = (const float*)d_in[7];
    const float* b_hh   = (const float*)d_in[8];
    const float* w_ae1  = (const float*)d_in[9];
    const float* b_ae1  = (const float*)d_in[10];
    const float* g_ae   = (const float*)d_in[11];
    const float* be_ae  = (const float*)d_in[12];
    const float* w_ae2  = (const float*)d_in[13];
    const float* b_ae2  = (const float*)d_in[14];
    const float* w_in1  = (const float*)d_in[15];
    const float* b_in1  = (const float*)d_in[16];
    const float* g_in   = (const float*)d_in[17];
    const float* be_in  = (const float*)d_in[18];
    const float* w_in2  = (const float*)d_in[19];
    const float* b_in2  = (const float*)d_in[20];
    const float* w_q    = (const float*)d_in[21];
    const float* w_k    = (const float*)d_in[22];
    const float* w_v    = (const float*)d_in[23];
    const float* w_fc   = (const float*)d_in[24];
    const float* gln    = (const float*)d_in[25];
    const float* bln    = (const float*)d_in[26];
    const float* w_mlp2 = (const float*)d_in[27];
    const float* b_mlp2 = (const float*)d_in[28];

    float* out  = (float*)d_out;
    float* qout = out;
    float* hout = out + HOFF;
    float* kout = out + KOFF;

    void *px1, *pt1, *pU, *pV, *pgx, *pgh;
    cudaGetSymbolAddress(&px1, g_x1);
    cudaGetSymbolAddress(&pt1, g_t1);
    cudaGetSymbolAddress(&pU, g_U);
    cudaGetSymbolAddress(&pV, g_V);
    cudaGetSymbolAddress(&pgx, g_gx);
    cudaGetSymbolAddress(&pgh, g_gh);

    size_t inf2_smem = (size_t)(128 * 136 + 64 * 132 + 1024 + 1024 + 8) * 4;
    size_t attn_smem = (size_t)(8192 * 4 + 128 + AT_WARPS * WSCR) * 4;
    cudaFuncSetAttribute(inf2_k, cudaFuncAttributeMaxDynamicSharedMemorySize, (int)inf2_smem);
    cudaFuncSetAttribute(attn_k, cudaFuncAttributeMaxDynamicSharedMemorySize, (int)attn_smem);

    // 1. x1 = relu(in @ w_mlp1 + b)
    gemm_k<1><<<dim3(1, 512), 128>>>(in_x, w_mlp1, b_mlp1, (float*)px1, BNR, 64, 96);
    // 2. gates
    gemm_k<0><<<dim3(3, 512), 128>>>((const float*)px1, w_ih, b_ih, (float*)pgx, BNR, 192, 64);
    gemm_k<0><<<dim3(3, 512), 128>>>(hid, w_hh, b_hh, (float*)pgh, BNR, 192, 64);
    // 3. GRU -> h (into d_out)
    gru_k<<<8192, 256>>>(hid, hout);
    // 4. ae1 (raw pre-BN output kept in g_t1)
    gemm_k<0><<<dim3(2, 512), 128>>>(hout, w_ae1, b_ae1, (float*)pt1, BNR, 128, 64);
    // 5. BN stats
    zero_stats_k<<<1, 1024>>>();
    ae_stats_k<<<128, 128>>>();
    fin_ae_k<<<1, 128>>>();
    // 6. ae2 (tf32 mma, BN+lrelu fused into A load) -> mean/var
    ae2_k<<<dim3(8, 256), 256>>>((const float*)pt1, w_ae2, b_ae2, g_ae, be_ae);
    // 7. awareness
    aware_k<<<16384, 256>>>(noise);
    // 8. U, V
    gemm_k<0><<<dim3(2, 512), 128>>>(hout, w_in1, nullptr, (float*)pU, BNR, 128, 64);
    gemm_k<0><<<dim3(2, 512), 128>>>(hout, w_in1 + 64 * 128, b_in1, (float*)pV, BNR, 128, 64);
    // 9. infer BN stats
    inf_stats_k<<<128, 128>>>();
    fin_inf_k<<<1, 128>>>();
    // 10. infer stage-2 (tf32 mma) + KLD
    inf2_k<<<4096, 256, inf2_smem>>>(w_in2, b_in2, g_in, be_in, kout);
    // 11. attention
    attn_k<<<296, 192, attn_smem>>>(w_q, w_k, w_v, w_fc, gln, bln);
    // 12. mlp2
    mlp2_k<<<256, 128>>>(hout, w_mlp2, b_mlp2, qout);
}

// round 5
// speedup vs baseline: 1.7091x; 1.3611x over previous
#include <cuda_runtime.h>
#include <math.h>
#include <stdint.h>

#define BNR 32768
#define HOFF 458752
#define KOFF 2555904

// ------------- scratch globals (no allocs allowed) -------------
__device__ __align__(16) float g_x1[BNR * 64];
__device__ __align__(16) float g_gx[BNR * 192];
__device__ __align__(16) float g_gh[BNR * 192];
__device__ __align__(16) float g_t1[BNR * 128];
__device__ __align__(16) float g_stats[1024];
__device__ __align__(16) float g_mean[BNR * 512];
__device__ __align__(16) float g_var[BNR * 512];
__device__ __align__(16) float g_aware[BNR * 512];
__device__ __align__(16) float g_att[BNR * 512];
__device__ __align__(16) float g_U[BNR * 128];
__device__ __align__(16) float g_V[BNR * 128];

// ------------- tf32 mma helpers -------------
__device__ __forceinline__ float f2tf(float x) {
    uint32_t r;
    asm("cvt.rna.tf32.f32 %0, %1;" : "=r"(r) : "f"(x));
    return __uint_as_float(r);
}
__device__ __forceinline__ void mma_tf32(float* c, const uint32_t* a, const uint32_t* b) {
    asm volatile(
        "mma.sync.aligned.m16n8k8.row.col.f32.tf32.tf32.f32 "
        "{%0,%1,%2,%3}, {%4,%5,%6,%7}, {%8,%9}, {%0,%1,%2,%3};"
        : "+f"(c[0]), "+f"(c[1]), "+f"(c[2]), "+f"(c[3])
        : "r"(a[0]), "r"(a[1]), "r"(a[2]), "r"(a[3]), "r"(b[0]), "r"(b[1]));
}

// ------------- small elementwise kernels -------------
__global__ void zero_stats_k() { g_stats[threadIdx.x] = 0.f; }

__global__ void __launch_bounds__(256) gru_k(const float* __restrict__ hin,
                                             float* __restrict__ hout) {
    int idx = blockIdx.x * 256 + threadIdx.x;        // < 32768*64
    int r = idx >> 6, j = idx & 63;
    int base = r * 192 + j;
    float xr = g_gx[base], xz = g_gx[base + 64], xn = g_gx[base + 128];
    float hr = g_gh[base], hz = g_gh[base + 64], hn = g_gh[base + 128];
    float rr = 1.f / (1.f + expf(-(xr + hr)));
    float zz = 1.f / (1.f + expf(-(xz + hz)));
    float nn = tanhf(xn + rr * hn);
    float hi = hin[idx];
    hout[idx] = (1.f - zz) * nn + zz * hi;
}

__global__ void __launch_bounds__(128) ae_stats_k() {
    int c = threadIdx.x;
    size_t r0 = (size_t)blockIdx.x * 256;
    float s1 = 0.f, s2 = 0.f;
    for (int r = 0; r < 256; r++) {
        float v = g_t1[(r0 + r) * 128 + c];
        s1 += v; s2 += v * v;
    }
    atomicAdd(&g_stats[c], s1);
    atomicAdd(&g_stats[128 + c], s2);
}

__global__ void fin_ae_k() {
    int c = threadIdx.x;
    float m = g_stats[c] * (1.f / 32768.f);
    float v = g_stats[128 + c] * (1.f / 32768.f) - m * m;
    g_stats[256 + c] = m;
    g_stats[384 + c] = rsqrtf(v + 1e-5f);
}

__global__ void __launch_bounds__(256) aware_k(const float* __restrict__ noise) {
    int i = blockIdx.x * 256 + threadIdx.x;          // float4 index < 4194304
    float4 m = ((const float4*)g_mean)[i];
    float4 v = ((const float4*)g_var)[i];
    float4 n = ((const float4*)noise)[i];
    float4 o;
    o.x = m.x + sqrtf(v.x) * n.x;
    o.y = m.y + sqrtf(v.y) * n.y;
    o.z = m.z + sqrtf(v.z) * n.z;
    o.w = m.w + sqrtf(v.w) * n.w;
    ((float4*)g_aware)[i] = o;
}

__global__ void __launch_bounds__(128) inf_stats_k() {
    int c = threadIdx.x;
    int b0 = blockIdx.x * 32;
    float A1 = 0.f, A2 = 0.f;
    for (int b = b0; b < b0 + 32; b++) {
        float su = 0.f, su2 = 0.f, sv = 0.f, sv2 = 0.f;
        #pragma unroll
        for (int i = 0; i < 8; i++) {
            float u = g_U[(size_t)(b * 8 + i) * 128 + c];
            float v = g_V[(size_t)(b * 8 + i) * 128 + c];
            su += u; su2 += u * u;
            sv += v; sv2 += v * v;
        }
        A1 += 8.f * (su + sv);
        A2 += 8.f * (su2 + sv2) + 2.f * su * sv;
    }
    atomicAdd(&g_stats[512 + c], A1);
    atomicAdd(&g_stats[640 + c], A2);
}

__global__ void fin_inf_k() {
    int c = threadIdx.x;
    const float im = 1.f / 262144.f;
    float m = g_stats[512 + c] * im;
    float v = g_stats[640 + c] * im - m * m;
    g_stats[768 + c] = m;
    g_stats[896 + c] = rsqrtf(v + 1e-5f);
}

// ------------- generic tiled SGEMM (small GEMMs): BM=BN=64, BK=16 -------------
template <int EPI>
__global__ void __launch_bounds__(128) gemm_k(
    const float* __restrict__ A, const float* __restrict__ B,
    const float* __restrict__ bias, float* __restrict__ C,
    int M, int N, int K) {
    __shared__ __align__(16) float As[16][68];
    __shared__ __align__(16) float Bs[16][68];
    int t = threadIdx.x;
    int m0 = blockIdx.y * 64, n0 = blockIdx.x * 64;
    int tx = t & 15, ty = t >> 4;
    float acc[8][4];
    #pragma unroll
    for (int i = 0; i < 8; i++)
        #pragma unroll
        for (int j = 0; j < 4; j++) acc[i][j] = 0.f;

    for (int k0 = 0; k0 < K; k0 += 16) {
        #pragma unroll
        for (int u = 0; u < 2; u++) {
            int f = t * 2 + u;
            int row = f >> 2, kq = (f & 3) * 4;
            float4 v = *(const float4*)(A + (size_t)(m0 + row) * K + k0 + kq);
            As[kq][row] = v.x; As[kq + 1][row] = v.y;
            As[kq + 2][row] = v.z; As[kq + 3][row] = v.w;
        }
        #pragma unroll
        for (int u = 0; u < 2; u++) {
            int f = t * 2 + u;
            int row = f >> 4, cq = (f & 15) * 4;
            *(float4*)&Bs[row][cq] = *(const float4*)(B + (size_t)(k0 + row) * N + n0 + cq);
        }
        __syncthreads();
        #pragma unroll
        for (int kk = 0; kk < 16; kk++) {
            float b4[4], a8[8];
            *(float4*)b4 = *(float4*)&Bs[kk][tx * 4];
            *(float4*)a8 = *(float4*)&As[kk][ty * 8];
            *(float4*)(a8 + 4) = *(float4*)&As[kk][ty * 8 + 4];
            #pragma unroll
            for (int i = 0; i < 8; i++)
                #pragma unroll
                for (int j = 0; j < 4; j++) acc[i][j] += a8[i] * b4[j];
        }
        __syncthreads();
    }
    #pragma unroll
    for (int i = 0; i < 8; i++) {
        int row = m0 + ty * 8 + i;
        #pragma unroll
        for (int j = 0; j < 4; j++) {
            int col = n0 + tx * 4 + j;
            float v = acc[i][j] + (bias ? bias[col] : 0.f);
            if (EPI == 1) v = v > 0.f ? v : 0.f;
            C[(size_t)row * N + col] = v;
        }
    }
}

// ------------- ae2: tf32 mma GEMM, BN+lrelu fused into A load ---------------
__global__ void __launch_bounds__(256) ae2_k(
    const float* __restrict__ Araw, const float* __restrict__ Bw,
    const float* __restrict__ bias,
    const float* __restrict__ gg, const float* __restrict__ bb) {
    __shared__ __align__(16) float As[128 * 36];
    __shared__ __align__(16) float Bs[32 * 136];
    __shared__ float sScale[128], sShift[128];
    int t = threadIdx.x, wid = t >> 5, lane = t & 31;
    int g = lane >> 2, tg = lane & 3;
    int m0 = blockIdx.y * 128, n0 = blockIdx.x * 128;
    int m0w = (wid & 3) * 32, n0w = (wid >> 2) * 64;

    if (t < 128) {
        float sc = g_stats[384 + t] * gg[t];
        sScale[t] = sc;
        sShift[t] = bb[t] - g_stats[256 + t] * sc;
    }
    __syncthreads();

    float acc[2][8][4];
    #pragma unroll
    for (int i = 0; i < 2; i++)
        #pragma unroll
        for (int j = 0; j < 8; j++)
            #pragma unroll
            for (int q = 0; q < 4; q++) acc[i][j][q] = 0.f;

    for (int k0 = 0; k0 < 128; k0 += 32) {
        #pragma unroll
        for (int u = 0; u < 4; u++) {
            int idx = t + u * 256;
            int row = idx >> 3, c4 = (idx & 7) * 4;
            float4 v = *(const float4*)(Araw + (size_t)(m0 + row) * 128 + k0 + c4);
            float vv[4] = {v.x, v.y, v.z, v.w};
            #pragma unroll
            for (int jj = 0; jj < 4; jj++) {
                int col = k0 + c4 + jj;
                float x = vv[jj] * sScale[col] + sShift[col];
                x = x >= 0.f ? x : 0.01f * x;
                As[row * 36 + c4 + jj] = f2tf(x);
            }
        }
        #pragma unroll
        for (int u = 0; u < 4; u++) {
            int idx = t + u * 256;
            int kr = idx >> 5, n4 = (idx & 31) * 4;
            float4 v = *(const float4*)(Bw + (size_t)(k0 + kr) * 1024 + n0 + n4);
            Bs[kr * 136 + n4 + 0] = f2tf(v.x);
            Bs[kr * 136 + n4 + 1] = f2tf(v.y);
            Bs[kr * 136 + n4 + 2] = f2tf(v.z);
            Bs[kr * 136 + n4 + 3] = f2tf(v.w);
        }
        __syncthreads();
        #pragma unroll
        for (int k8 = 0; k8 < 4; k8++) {
            int kb = k8 * 8;
            uint32_t af[2][4];
            #pragma unroll
            for (int i = 0; i < 2; i++) {
                int base = (m0w + i * 16 + g) * 36 + kb + tg;
                af[i][0] = __float_as_uint(As[base]);
                af[i][1] = __float_as_uint(As[base + 8 * 36]);
                af[i][2] = __float_as_uint(As[base + 4]);
                af[i][3] = __float_as_uint(As[base + 8 * 36 + 4]);
            }
            #pragma unroll
            for (int j = 0; j < 8; j++) {
                uint32_t bf[2];
                int nb = n0w + j * 8 + g;
                bf[0] = __float_as_uint(Bs[(kb + tg) * 136 + nb]);
                bf[1] = __float_as_uint(Bs[(kb + tg + 4) * 136 + nb]);
                mma_tf32(acc[0][j], af[0], bf);
                mma_tf32(acc[1][j], af[1], bf);
            }
        }
        __syncthreads();
    }
    bool isvar = (n0 >= 512);
    #pragma unroll
    for (int i = 0; i < 2; i++) {
        #pragma unroll
        for (int j = 0; j < 8; j++) {
            int col = n0 + n0w + j * 8 + 2 * tg;
            float b0 = bias[col], b1 = bias[col + 1];
            int r0 = m0 + m0w + i * 16 + g;
            float v00 = acc[i][j][0] + b0, v01 = acc[i][j][1] + b1;
            float v10 = acc[i][j][2] + b0, v11 = acc[i][j][3] + b1;
            if (isvar) {
                int c = col - 512;
                *(float2*)&g_var[(size_t)r0 * 512 + c] =
                    make_float2(fmaxf(expf(v00), 0.002f), fmaxf(expf(v01), 0.002f));
                *(float2*)&g_var[(size_t)(r0 + 8) * 512 + c] =
                    make_float2(fmaxf(expf(v10), 0.002f), fmaxf(expf(v11), 0.002f));
            } else {
                *(float2*)&g_mean[(size_t)r0 * 512 + col] = make_float2(v00, v01);
                *(float2*)&g_mean[(size_t)(r0 + 8) * 512 + col] = make_float2(v10, v11);
            }
        }
    }
}

// ------------- infer stage-2 (tf32 mma) fused with KLD (one block per b) -----
__global__ void __launch_bounds__(256) inf2_k(
    const float* __restrict__ w2, const float* __restrict__ b2,
    const float* __restrict__ gi, const float* __restrict__ bei,
    float* __restrict__ kout) {
    extern __shared__ __align__(16) float sm[];
    float* sW  = sm;                  // [128][136]
    float* sA2 = sW + 128 * 136;      // [64][132]
    float* sU  = sA2 + 64 * 132;      // [8][128]
    float* sV  = sU + 1024;
    float* sred = sV + 1024;          // 8
    int t = threadIdx.x, b = blockIdx.x;
    int wid = t >> 5, lane = t & 31;
    int g = lane >> 2, tg = lane & 3;

    for (int i = t; i < 1024; i += 256) {
        sU[i] = g_U[(size_t)b * 1024 + i];
        sV[i] = g_V[(size_t)b * 1024 + i];
    }
    #pragma unroll
    for (int u = 0; u < 16; u++) {
        int idx = t + u * 256;
        int row = idx >> 5, c4 = (idx & 31) * 4;
        float4 v = *(const float4*)(w2 + row * 128 + c4);
        sW[row * 136 + c4 + 0] = f2tf(v.x);
        sW[row * 136 + c4 + 1] = f2tf(v.y);
        sW[row * 136 + c4 + 2] = f2tf(v.z);
        sW[row * 136 + c4 + 3] = f2tf(v.w);
    }
    __syncthreads();
    for (int e = t; e < 8192; e += 256) {
        int row = e >> 7, c = e & 127;
        int i = row >> 3, j = row & 7;
        float v = (sU[i * 128 + c] + sV[j * 128 + c] - g_stats[768 + c]) *
                  g_stats[896 + c] * gi[c] + bei[c];
        v = v >= 0.f ? v : 0.01f * v;
        sA2[row * 132 + c] = f2tf(v);
    }
    __syncthreads();

    int mt = wid & 3, n0w = (wid >> 2) * 64;
    float acc[8][4];
    #pragma unroll
    for (int j = 0; j < 8; j++)
        #pragma unroll
        for (int q = 0; q < 4; q++) acc[j][q] = 0.f;
    #pragma unroll
    for (int k8 = 0; k8 < 16; k8++) {
        int kb = k8 * 8;
        uint32_t af[4];
        int base = (mt * 16 + g) * 132 + kb + tg;
        af[0] = __float_as_uint(sA2[base]);
        af[1] = __float_as_uint(sA2[base + 8 * 132]);
        af[2] = __float_as_uint(sA2[base + 4]);
        af[3] = __float_as_uint(sA2[base + 8 * 132 + 4]);
        #pragma unroll
        for (int j = 0; j < 8; j++) {
            uint32_t bf[2];
            int nb = n0w + j * 8 + g;
            bf[0] = __float_as_uint(sW[(kb + tg) * 136 + nb]);
            bf[1] = __float_as_uint(sW[(kb + tg + 4) * 136 + nb]);
            mma_tf32(acc[j], af, bf);
        }
    }
    __syncthreads();
    #pragma unroll
    for (int j = 0; j < 8; j++) {
        int col = n0w + j * 8 + 2 * tg;
        int r0 = mt * 16 + g;
        sA2[r0 * 132 + col] = acc[j][0] + b2[col];
        sA2[r0 * 132 + col + 1] = acc[j][1] + b2[col + 1];
        sA2[(r0 + 8) * 132 + col] = acc[j][2] + b2[col];
        sA2[(r0 + 8) * 132 + col + 1] = acc[j][3] + b2[col + 1];
    }
    __syncthreads();

    float s = 0.f;
    for (int e = t; e < 4096; e += 256) {
        int row = e >> 6, d = e & 63;
        float im = sA2[row * 132 + d];
        float iv = fmaxf(expf(sA2[row * 132 + 64 + d]), 0.002f);
        int i = row >> 3, j = row & 7;
        size_t gr = (size_t)(b * 8 + i) * 512 + j * 64 + d;
        float m = g_mean[gr], v = g_var[gr];
        float dd = m - im;
        s += 0.5f * (logf(iv) - logf(v)) + 0.5f * (v + dd * dd) / iv - 0.5f;
    }
    for (int off = 16; off; off >>= 1) s += __shfl_xor_sync(~0u, s, off);
    if ((t & 31) == 0) sred[t >> 5] = s;
    __syncthreads();
    if (t < 8) {
        s = sred[t];
        #pragma unroll
        for (int off = 4; off; off >>= 1) s += __shfl_xor_sync(0xffu, s, off);
        if (t == 0) kout[b] = s * (1.f / 4096.f);
    }
}

// ------------- attention v2: 8 rows (64 tokens) per block, tf32 mma ---------
// smem layout (floats):
//   sA   [64][68]   0      (fp32 awareness tile; residual source)
//   sW   8704       4352   (streamed weight: 64x128 s132 for QKV, 128x68 wfc)
//   sQ   [64][132]  13056  (head-offset layout h*33+d; later holds O)
//   sK   [64][132]  21504  (later holds F+residual)
//   sV   [64][132]  29952
//   sgln 64         38400,  sbln 64  38464   -> total 38528 floats
__global__ void __launch_bounds__(256) attn2_k(
    const float* __restrict__ wq, const float* __restrict__ wk,
    const float* __restrict__ wv, const float* __restrict__ wfc,
    const float* __restrict__ gln, const float* __restrict__ bln) {
    extern __shared__ __align__(16) float sm[];
    float* sA = sm;
    float* sW = sm + 4352;
    float* sQ = sm + 13056;
    float* sK = sm + 21504;
    float* sV = sm + 29952;
    float* sgln = sm + 38400;
    float* sbln = sm + 38464;
    int t = threadIdx.x, wid = t >> 5, lane = t & 31;
    int g = lane >> 2, tg = lane & 3;
    int mw = (wid & 3) * 16;
    int nw2 = wid >> 2;                        // 0/1 (n-half for QKV)
    size_t rbase = (size_t)blockIdx.x * 8;

    // load A tile (fp32) + ln params
    #pragma unroll
    for (int u = 0; u < 4; u++) {
        int i = t + u * 256;                    // float4 id
        int tok = i >> 4, c4 = (i & 15) * 4;
        float4 v = *(const float4*)(g_aware + rbase * 512 + tok * 64 + c4);
        *(float4*)&sA[tok * 68 + c4] = v;
    }
    if (t < 64) sgln[t] = gln[t];
    else if (t < 128) sbln[t - 64] = bln[t - 64];

    // ---- QKV: three 64x128x64 mma GEMMs, weight streamed through sW ----
    const float* Wsrc[3] = {wq, wk, wv};
    float* Dst[3] = {sQ, sK, sV};
    for (int w = 0; w < 3; w++) {
        #pragma unroll
        for (int u = 0; u < 8; u++) {
            int i = t + u * 256;
            int row = i >> 5, c4 = (i & 31) * 4;
            float4 v = *(const float4*)(Wsrc[w] + row * 128 + c4);
            sW[row * 132 + c4 + 0] = f2tf(v.x);
            sW[row * 132 + c4 + 1] = f2tf(v.y);
            sW[row * 132 + c4 + 2] = f2tf(v.z);
            sW[row * 132 + c4 + 3] = f2tf(v.w);
        }
        __syncthreads();
        float acc[8][4];
        #pragma unroll
        for (int j = 0; j < 8; j++)
            #pragma unroll
            for (int q = 0; q < 4; q++) acc[j][q] = 0.f;
        #pragma unroll
        for (int k8 = 0; k8 < 8; k8++) {
            int kb = k8 * 8;
            uint32_t af[4];
            int base = (mw + g) * 68 + kb + tg;
            af[0] = __float_as_uint(f2tf(sA[base]));
            af[1] = __float_as_uint(f2tf(sA[base + 8 * 68]));
            af[2] = __float_as_uint(f2tf(sA[base + 4]));
            af[3] = __float_as_uint(f2tf(sA[base + 8 * 68 + 4]));
            #pragma unroll
            for (int j = 0; j < 8; j++) {
                int nb = nw2 * 64 + j * 8 + g;
                uint32_t bf[2];
                bf[0] = __float_as_uint(sW[(kb + tg) * 132 + nb]);
                bf[1] = __float_as_uint(sW[(kb + tg + 4) * 132 + nb]);
                mma_tf32(acc[j], af, bf);
            }
        }
        float* D = Dst[w];
        #pragma unroll
        for (int j = 0; j < 8; j++) {
            int col = nw2 * 64 + j * 8 + 2 * tg;           // even, pair stays in chunk
            int cm = (col >> 5) * 33 + (col & 31);          // head-offset mapping
            D[(mw + g) * 132 + cm] = acc[j][0];
            D[(mw + g) * 132 + cm + 1] = acc[j][1];
            D[(mw + g + 8) * 132 + cm] = acc[j][2];
            D[(mw + g + 8) * 132 + cm + 1] = acc[j][3];
        }
        __syncthreads();
    }

    // ---- scores + softmax (thread = (row, head, q)) ----
    int srow = wid;                 // 0..7
    int h = (t >> 3) & 3, q = t & 7;
    int tokq = srow * 8 + q;
    float qd[32];
    #pragma unroll
    for (int d = 0; d < 32; d++) qd[d] = sQ[tokq * 132 + h * 33 + d];
    float p[8];
    #pragma unroll
    for (int k = 0; k < 8; k++) {
        int tokk = srow * 8 + k;
        float s = 0.f;
        #pragma unroll
        for (int d = 0; d < 32; d++) s += qd[d] * sK[tokk * 132 + h * 33 + d];
        p[k] = s * 0.17677669529663687f;
    }
    float mx = p[0];
    #pragma unroll
    for (int k = 1; k < 8; k++) mx = fmaxf(mx, p[k]);
    float ssum = 0.f;
    #pragma unroll
    for (int k = 0; k < 8; k++) { p[k] = __expf(p[k] - mx); ssum += p[k]; }
    float inv = 1.f / ssum;
    #pragma unroll
    for (int k = 0; k < 8; k++) p[k] *= inv;
    __syncthreads();                 // all sQ reads done

    // ---- AV: O overwrites sQ (tf32-rounded) ----
    #pragma unroll
    for (int d = 0; d < 32; d++) {
        float o = 0.f;
        #pragma unroll
        for (int k = 0; k < 8; k++)
            o += p[k] * sV[(srow * 8 + k) * 132 + h * 33 + d];
        sQ[tokq * 132 + h * 33 + d] = f2tf(o);
    }

    // ---- load wfc (128x64, stride 68) ----
    #pragma unroll
    for (int u = 0; u < 8; u++) {
        int i = t + u * 256;
        int row = i >> 4, c4 = (i & 15) * 4;
        float4 v = *(const float4*)(wfc + row * 64 + c4);
        sW[row * 68 + c4 + 0] = f2tf(v.x);
        sW[row * 68 + c4 + 1] = f2tf(v.y);
        sW[row * 68 + c4 + 2] = f2tf(v.z);
        sW[row * 68 + c4 + 3] = f2tf(v.w);
    }
    __syncthreads();

    // ---- fc: F(64x64) = O(64x128) @ wfc(128x64) ----
    int nwf = (wid >> 2) * 32;
    float acc2[4][4];
    #pragma unroll
    for (int j = 0; j < 4; j++)
        #pragma unroll
        for (int q2 = 0; q2 < 4; q2++) acc2[j][q2] = 0.f;
    #pragma unroll
    for (int k8 = 0; k8 < 16; k8++) {
        int kb = k8 * 8;
        int cmk = (kb >> 5) * 33 + (kb & 31);        // mapped k base (8-block stays in chunk)
        uint32_t af[4];
        int b0 = (mw + g) * 132 + cmk + tg;
        af[0] = __float_as_uint(sQ[b0]);
        af[1] = __float_as_uint(sQ[b0 + 8 * 132]);
        af[2] = __float_as_uint(sQ[b0 + 4]);
        af[3] = __float_as_uint(sQ[b0 + 8 * 132 + 4]);
        #pragma unroll
        for (int j = 0; j < 4; j++) {
            int nb = nwf + j * 8 + g;
            uint32_t bf[2];
            bf[0] = __float_as_uint(sW[(kb + tg) * 68 + nb]);
            bf[1] = __float_as_uint(sW[(kb + tg + 4) * 68 + nb]);
            mma_tf32(acc2[j], af, bf);
        }
    }
    __syncthreads();                 // sK reads (scores) long done; safe to overwrite
    #pragma unroll
    for (int j = 0; j < 4; j++) {
        int col = nwf + j * 8 + 2 * tg;
        int tok = mw + g;
        sK[tok * 132 + col]     = acc2[j][0] + sA[tok * 68 + col];
        sK[tok * 132 + col + 1] = acc2[j][1] + sA[tok * 68 + col + 1];
        sK[(tok + 8) * 132 + col]     = acc2[j][2] + sA[(tok + 8) * 68 + col];
        sK[(tok + 8) * 132 + col + 1] = acc2[j][3] + sA[(tok + 8) * 68 + col + 1];
    }
    __syncthreads();

    // ---- LayerNorm: 4 threads per token ----
    int tok = t >> 2, part = t & 3;
    float vals[16];
    float s1 = 0.f, s2 = 0.f;
    #pragma unroll
    for (int i = 0; i < 16; i++) {
        float v = sK[tok * 132 + part * 16 + i];
        vals[i] = v; s1 += v; s2 += v * v;
    }
    s1 += __shfl_xor_sync(~0u, s1, 1); s2 += __shfl_xor_sync(~0u, s2, 1);
    s1 += __shfl_xor_sync(~0u, s1, 2); s2 += __shfl_xor_sync(~0u, s2, 2);
    float mu = s1 * (1.f / 64.f);
    float var = s2 * (1.f / 64.f) - mu * mu;
    float is = rsqrtf(var + 1e-6f);
    int row = tok >> 3, agent = tok & 7;
    float* outp = g_att + (rbase + row) * 512 + agent * 64 + part * 16;
    #pragma unroll
    for (int i = 0; i < 16; i++)
        outp[i] = (vals[i] - mu) * is * sgln[part * 16 + i] + sbln[part * 16 + i];
}

// ------------- mlp2: q = [h | att] @ w_mlp2 + b -------------
__global__ void __launch_bounds__(128) mlp2_k(
    const float* __restrict__ h, const float* __restrict__ w,
    const float* __restrict__ b, float* __restrict__ out) {
    __shared__ __align__(16) float As[128][68];
    __shared__ __align__(16) float Ws[64][16];
    __shared__ float sb[14];
    int t = threadIdx.x;
    int r0 = blockIdx.x * 128;
    if (t < 14) sb[t] = b[t];
    int rg = t >> 2, cg = t & 3;
    float acc[4][4];
    #pragma unroll
    for (int i = 0; i < 4; i++)
        #pragma unroll
        for (int j = 0; j < 4; j++) acc[i][j] = 0.f;

    for (int k0 = 0; k0 < 576; k0 += 64) {
        #pragma unroll
        for (int u = 0; u < 16; u++) {
            int f = u * 128 + t;
            int row = f >> 4, cq = (f & 15) * 4;
            float4 v;
            if (k0 == 0) v = *(const float4*)(h + (size_t)(r0 + row) * 64 + cq);
            else v = *(const float4*)(g_att + (size_t)(r0 + row) * 512 + (k0 - 64) + cq);
            *(float4*)&As[row][cq] = v;
        }
        for (int i = t; i < 1024; i += 128) {
            int row = i >> 4, c = i & 15;
            Ws[row][c] = (c < 14) ? w[(k0 + row) * 14 + c] : 0.f;
        }
        __syncthreads();
        #pragma unroll
        for (int kk = 0; kk < 64; kk++) {
            float a4[4], w4[4];
            #pragma unroll
            for (int i = 0; i < 4; i++) a4[i] = As[rg * 4 + i][kk];
            *(float4*)w4 = *(float4*)&Ws[kk][cg * 4];
            #pragma unroll
            for (int i = 0; i < 4; i++)
                #pragma unroll
                for (int j = 0; j < 4; j++) acc[i][j] += a4[i] * w4[j];
        }
        __syncthreads();
    }
    #pragma unroll
    for (int i = 0; i < 4; i++) {
        int row = r0 + rg * 4 + i;
        #pragma unroll
        for (int j = 0; j < 4; j++) {
            int col = cg * 4 + j;
            if (col < 14) out[(size_t)row * 14 + col] = acc[i][j] + sb[col];
        }
    }
}

// ------------- launcher -------------
extern "C" void kernel_launch(void* const* d_in, const int* in_sizes, int n_in,
                              void* d_out, int out_size) {
    const float* in_x   = (const float*)d_in[0];
    const float* hid    = (const float*)d_in[1];
    const float* noise  = (const float*)d_in[2];
    const float* w_mlp1 = (const float*)d_in[3];
    const float* b_mlp1 = (const float*)d_in[4];
    const float* w_ih   = (const float*)d_in[5];
    const float* b_ih   = (const float*)d_in[6];
    const float* w_hh   = (const float*)d_in[7];
    const float* b_hh   = (const float*)d_in[8];
    const float* w_ae1  = (const float*)d_in[9];
    const float* b_ae1  = (const float*)d_in[10];
    const float* g_ae   = (const float*)d_in[11];
    const float* be_ae  = (const float*)d_in[12];
    const float* w_ae2  = (const float*)d_in[13];
    const float* b_ae2  = (const float*)d_in[14];
    const float* w_in1  = (const float*)d_in[15];
    const float* b_in1  = (const float*)d_in[16];
    const float* g_in   = (const float*)d_in[17];
    const float* be_in  = (const float*)d_in[18];
    const float* w_in2  = (const float*)d_in[19];
    const float* b_in2  = (const float*)d_in[20];
    const float* w_q    = (const float*)d_in[21];
    const float* w_k    = (const float*)d_in[22];
    const float* w_v    = (const float*)d_in[23];
    const float* w_fc   = (const float*)d_in[24];
    const float* gln    = (const float*)d_in[25];
    const float* bln    = (const float*)d_in[26];
    const float* w_mlp2 = (const float*)d_in[27];
    const float* b_mlp2 = (const float*)d_in[28];

    float* out  = (float*)d_out;
    float* qout = out;
    float* hout = out + HOFF;
    float* kout = out + KOFF;

    void *px1, *pt1, *pU, *pV, *pgx, *pgh;
    cudaGetSymbolAddress(&px1, g_x1);
    cudaGetSymbolAddress(&pt1, g_t1);
    cudaGetSymbolAddress(&pU, g_U);
    cudaGetSymbolAddress(&pV, g_V);
    cudaGetSymbolAddress(&pgx, g_gx);
    cudaGetSymbolAddress(&pgh, g_gh);

    size_t inf2_smem = (size_t)(128 * 136 + 64 * 132 + 1024 + 1024 + 8) * 4;
    size_t attn_smem = (size_t)38528 * 4;     // 154112 B
    cudaFuncSetAttribute(inf2_k, cudaFuncAttributeMaxDynamicSharedMemorySize, (int)inf2_smem);
    cudaFuncSetAttribute(attn2_k, cudaFuncAttributeMaxDynamicSharedMemorySize, (int)attn_smem);

    gemm_k<1><<<dim3(1, 512), 128>>>(in_x, w_mlp1, b_mlp1, (float*)px1, BNR, 64, 96);
    gemm_k<0><<<dim3(3, 512), 128>>>((const float*)px1, w_ih, b_ih, (float*)pgx, BNR, 192, 64);
    gemm_k<0><<<dim3(3, 512), 128>>>(hid, w_hh, b_hh, (float*)pgh, BNR, 192, 64);
    gru_k<<<8192, 256>>>(hid, hout);
    gemm_k<0><<<dim3(2, 512), 128>>>(hout, w_ae1, b_ae1, (float*)pt1, BNR, 128, 64);
    zero_stats_k<<<1, 1024>>>();
    ae_stats_k<<<128, 128>>>();
    fin_ae_k<<<1, 128>>>();
    ae2_k<<<dim3(8, 256), 256>>>((const float*)pt1, w_ae2, b_ae2, g_ae, be_ae);
    aware_k<<<16384, 256>>>(noise);
    gemm_k<0><<<dim3(2, 512), 128>>>(hout, w_in1, nullptr, (float*)pU, BNR, 128, 64);
    gemm_k<0><<<dim3(2, 512), 128>>>(hout, w_in1 + 64 * 128, b_in1, (float*)pV, BNR, 128, 64);
    inf_stats_k<<<128, 128>>>();
    fin_inf_k<<<1, 128>>>();
    inf2_k<<<4096, 256, inf2_smem>>>(w_in2, b_in2, g_in, be_in, kout);
    attn2_k<<<4096, 256, attn_smem>>>(w_q, w_k, w_v, w_fc, gln, bln);
    mlp2_k<<<256, 128>>>(hout, w_mlp2, b_mlp2, qout);
}